// round 17
// baseline (speedup 1.0000x reference)
#include <cuda_runtime.h>
#include <cuda_fp16.h>
#include <cstdint>

// Problem constants
#define BB 64
#define SS 1024
#define CC 512
#define SC (SS*CC)
#define NN (BB*CC)          // 32768 = total N of the big GEMM
#define EPS 1e-5f
#define BK 32               // k-tile (halves)
#define NT (SS / BK)        // 32 k-tiles

#define PCTAS 512           // persistent prepass grid (1-wave resident)
#define CHUNKS_PER_B 8      // PCTAS / BB

// Scratch (device globals; 16B-aligned for cp.async / uint4)
__device__ float2 g_partials[PCTAS];
__device__ unsigned g_arrive;   // monotonic ticket counter (never reset)
// K-panel layouts: [(kt*ROWS + row)*32 + ks], fp16
__device__ __align__(16) __half g_Hp[(size_t)NN * SS];     // B panels (64MB)
__device__ __align__(16) __half g_Wh[(size_t)SS * SS];     // A panels (2MB)

// ---------------------------------------------------------------------------
// helpers
// ---------------------------------------------------------------------------
__device__ __forceinline__ uint32_t smem_to_u32(const void* p) {
    uint32_t a;
    asm("{ .reg .u64 t; cvta.to.shared.u64 t, %1; cvt.u32.u64 %0, t; }" : "=r"(a) : "l"(p));
    return a;
}
__device__ __forceinline__ void ldmatrix_x4(uint32_t& r0, uint32_t& r1,
                                            uint32_t& r2, uint32_t& r3, uint32_t addr) {
    asm volatile("ldmatrix.sync.aligned.m8n8.x4.shared.b16 {%0,%1,%2,%3}, [%4];"
                 : "=r"(r0), "=r"(r1), "=r"(r2), "=r"(r3) : "r"(addr));
}
__device__ __forceinline__ void mma_f16(float* d, const uint32_t* a,
                                        uint32_t b0, uint32_t b1) {
    asm volatile(
        "mma.sync.aligned.m16n8k16.row.col.f32.f16.f16.f32 "
        "{%0,%1,%2,%3}, {%4,%5,%6,%7}, {%8,%9}, {%0,%1,%2,%3};"
        : "+f"(d[0]), "+f"(d[1]), "+f"(d[2]), "+f"(d[3])
        : "r"(a[0]), "r"(a[1]), "r"(a[2]), "r"(a[3]), "r"(b0), "r"(b1));
}
__device__ __forceinline__ void cp16(uint32_t dst, const void* src) {
    asm volatile("cp.async.cg.shared.global [%0], [%1], 16;" :: "r"(dst), "l"(src));
}
#define CP_COMMIT() asm volatile("cp.async.commit_group;" ::: "memory")
#define CP_WAIT1()  asm volatile("cp.async.wait_group 1;" ::: "memory")

__device__ __forceinline__ uint32_t pack2(float a, float b) {
    __half2 h = __floats2half2_rn(a, b);
    return *reinterpret_cast<uint32_t*>(&h);
}

// ---------------------------------------------------------------------------
// Kernel 1: PERSISTENT fused prepass. grid = PCTAS (512) CTAs x 256 threads,
// guaranteed single-wave resident (4 CTAs/SM x 148 SMs = 592 slots).
//   Phase A: per-slice reduce (sum,sumsq) of x  +  convert 2 W tiles -> g_Wh.
//   Device-wide ticket barrier (monotonic counter; graph-replay safe).
//   Phase B: stats (mu, rstd) for this CTA's batch.
//   Phase C: normalize+transpose the SAME x slice -> g_Hp K-panels.
//            x slice (256KB) is L2-resident from phase A -> no DRAM re-read.
// ---------------------------------------------------------------------------
__global__ __launch_bounds__(256, 4)
void prepass_kernel(const float* __restrict__ x, const float* __restrict__ W,
                    const float* __restrict__ lnw, const float* __restrict__ lnb)
{
    const int tid    = threadIdx.x;
    const int cta    = blockIdx.x;
    const int b      = cta >> 3;            // 0..63
    const int chunk  = cta & 7;             // 0..7
    const int s_base = chunk * 128;         // 128 s-rows per slice

    __shared__ float red_s[8], red_sq[8];
    __shared__ float wtile[32][33];
    __shared__ float tile[32][65];
    __shared__ float2 sstat;

    // ---------- Phase A1: reduce this slice (128 s-rows x 512 c) ----------
    {
        const float4* px = reinterpret_cast<const float4*>(
            x + (size_t)b * SC + (size_t)s_base * CC);
        float s = 0.f, sq = 0.f;
        #pragma unroll 4
        for (int i = tid; i < 16384; i += 256) {     // 16384 float4 per slice
            float4 v = px[i];
            s  += v.x + v.y + v.z + v.w;
            sq += v.x*v.x + v.y*v.y + v.z*v.z + v.w*v.w;
        }
        #pragma unroll
        for (int o = 16; o > 0; o >>= 1) {
            s  += __shfl_down_sync(0xffffffff, s,  o);
            sq += __shfl_down_sync(0xffffffff, sq, o);
        }
        if ((tid & 31) == 0) { red_s[tid >> 5] = s; red_sq[tid >> 5] = sq; }
        __syncthreads();
        if (tid == 0) {
            float ts = 0.f, tsq = 0.f;
            #pragma unroll
            for (int w = 0; w < 8; w++) { ts += red_s[w]; tsq += red_sq[w]; }
            g_partials[cta] = make_float2(ts, tsq);
        }
    }

    // ---------- Phase A2: convert 2 W tiles (32x32 each) -> g_Wh ----------
    {
        const int tx = tid & 31;
        const int ty = tid >> 5;             // 0..7
        #pragma unroll
        for (int w2 = 0; w2 < 2; w2++) {
            const int wt = cta * 2 + w2;     // 0..1023
            const int m0 = (wt >> 5) * 32;
            const int s0 = (wt & 31) * 32;
            __syncthreads();                 // prior readers of wtile done
            #pragma unroll
            for (int i = 0; i < 4; i++)
                wtile[ty + i * 8][tx] = W[(size_t)(m0 + ty + i * 8) * SS + s0 + tx];
            __syncthreads();
            if (tid < 128) {
                const int m  = tid >> 2;
                const int ch = tid & 3;
                const int kt = s0 >> 5;
                uint4 pk;
                pk.x = pack2(wtile[m][ch*8+0], wtile[m][ch*8+1]);
                pk.y = pack2(wtile[m][ch*8+2], wtile[m][ch*8+3]);
                pk.z = pack2(wtile[m][ch*8+4], wtile[m][ch*8+5]);
                pk.w = pack2(wtile[m][ch*8+6], wtile[m][ch*8+7]);
                *reinterpret_cast<uint4*>(g_Wh + ((size_t)kt * SS + m0 + m) * 32 + ch * 8) = pk;
            }
        }
    }

    // ---------- Device-wide ticket barrier (graph-replay safe) ----------
    __threadfence();
    __syncthreads();
    if (tid == 0) {
        unsigned t = atomicAdd(&g_arrive, 1u);
        unsigned target = (t / PCTAS) * PCTAS + PCTAS;
        while (*(volatile unsigned*)&g_arrive < target) {}
    }
    __syncthreads();
    __threadfence();

    // ---------- Phase B: stats for batch b ----------
    if (tid == 0) {
        float s = 0.f, sq = 0.f;
        #pragma unroll
        for (int j = 0; j < CHUNKS_PER_B; j++) {
            float2 p = g_partials[b * CHUNKS_PER_B + j];
            s += p.x; sq += p.y;
        }
        float mu  = s / (float)SC;
        float var = fmaxf(sq / (float)SC - mu * mu, 0.f);
        sstat = make_float2(mu, rsqrtf(var + EPS));
    }
    __syncthreads();
    const float2 st = sstat;

    // ---------- Phase C: normalize+transpose slice -> g_Hp ----------
    // 4 s-subtiles (k-panels) x 8 c-subtiles of 32(s) x 64(c).
    const int tx64 = tid & 63;
    const int ty4  = tid >> 6;               // 0..3
    for (int ssub = 0; ssub < 4; ssub++) {
        const int s0 = s_base + ssub * 32;
        const int kt = s0 >> 5;
        for (int csub = 0; csub < 8; csub++) {
            const int c0 = csub * 64;
            __syncthreads();                  // prior write-phase reads done
            #pragma unroll
            for (int i = 0; i < 8; i++) {
                int sl = ty4 + i * 4;         // 0..31
                int sg = s0 + sl;
                int cg = c0 + tx64;
                float v  = x  [(size_t)b * SC + (size_t)sg * CC + cg];
                float w  = lnw[(size_t)sg * CC + cg];
                float bb = lnb[(size_t)sg * CC + cg];
                tile[sl][tx64] = (v - st.x) * st.y * w + bb;
            }
            __syncthreads();
            const int c   = tid >> 2;         // 0..63
            const int ch4 = tid & 3;          // 0..3
            const int n   = b * CC + c0 + c;
            uint4 pk;
            pk.x = pack2(tile[ch4*8+0][c], tile[ch4*8+1][c]);
            pk.y = pack2(tile[ch4*8+2][c], tile[ch4*8+3][c]);
            pk.z = pack2(tile[ch4*8+4][c], tile[ch4*8+5][c]);
            pk.w = pack2(tile[ch4*8+6][c], tile[ch4*8+7][c]);
            *reinterpret_cast<uint4*>(g_Hp + ((size_t)kt * NN + n) * 32 + ch4 * 8) = pk;
        }
    }
}

// ---------------------------------------------------------------------------
// Kernel 2: fp16 GEMM, fp32 acc. D[1024, 32768] = Wh x Hp^T, K=1024.
// CTA 128(M) x 128(N) x 32(K). 128 threads, 4 warps (2M x 2N), warp 64x64.
// Register fragment double-buffer. 2 CTAs/SM. 3-stage cp.async.
// 80B smem rows (conflict-free ldmatrix).   [R11 — byte-identical, frozen]
// Epilogue: out = x + relu(D + bias).
// ---------------------------------------------------------------------------
#define BM 128
#define BN 128
#define AST (BM * 80)              // 10240 B per A stage
#define BST (BN * 80)              // 10240 B per B stage
#define NSTG 3
#define OFF_BS (NSTG * AST)        // B stages base
#define GSMEM (NSTG * (AST + BST)) // 61440 B -> 2 CTAs = 120KB

__global__ __launch_bounds__(128, 2)
void gemm_f16(const float* __restrict__ linb,
              const float* __restrict__ x, float* __restrict__ out)
{
    extern __shared__ char smem[];
    const uint32_t sb = smem_to_u32(smem);

    const int tid  = threadIdx.x;
    const int lane = tid & 31;
    const int wid  = tid >> 5;          // 0..3
    const int wm   = (wid >> 1) * 64;   // 0 / 64
    const int wn   = (wid & 1) * 64;    // 0 / 64
    const int m0   = blockIdx.x * BM;
    const int n0   = blockIdx.y * BN;

    float acc[4][8][4];
    #pragma unroll
    for (int i = 0; i < 4; i++)
        #pragma unroll
        for (int j = 0; j < 8; j++)
            #pragma unroll
            for (int k = 0; k < 4; k++) acc[i][j][k] = 0.f;

    const __half* Apan = g_Wh + ((size_t)m0) * 32;  // + t*SS*32 per tile
    const __half* Bpan = g_Hp + ((size_t)n0) * 32;  // + t*NN*32 per tile

    // cp.async: 512 A tasks + 512 B tasks over 128 threads = 4+4 per thread.
    #define ISSUE(t, st)                                                          \
        do {                                                                      \
            const __half* asrc = Apan + (size_t)(t) * SS * 32;                    \
            const __half* bsrc = Bpan + (size_t)(t) * NN * 32;                    \
            _Pragma("unroll")                                                     \
            for (int k = 0; k < 4; k++) {                                         \
                int idx = k * 128 + tid;                                          \
                int row = idx >> 2, ch = idx & 3;                                 \
                cp16(sb + (st) * AST + row * 80 + ch * 16,                        \
                     asrc + (size_t)row * 32 + ch * 8);                           \
                cp16(sb + OFF_BS + (st) * BST + row * 80 + ch * 16,               \
                     bsrc + (size_t)row * 32 + ch * 8);                           \
            }                                                                     \
        } while (0)

    // ldmatrix base addresses
    const int l15 = lane & 15;
    const int lhi = lane >> 4;
    const uint32_t aLd = sb + (wm + l15) * 80 + lhi * 16;
    const uint32_t bLd = sb + OFF_BS + (wn + l15) * 80 + lhi * 16;

    // fragment double buffers
    uint32_t af[2][16], bf[2][16];

    #define LOAD_FRAGS(buf, st, ks)                                               \
        do {                                                                      \
            _Pragma("unroll")                                                     \
            for (int i = 0; i < 4; i++)                                           \
                ldmatrix_x4(af[buf][i*4+0], af[buf][i*4+1],                       \
                            af[buf][i*4+2], af[buf][i*4+3],                       \
                            aLd + (st) * AST + i * 16 * 80 + (ks) * 32);          \
            _Pragma("unroll")                                                     \
            for (int j = 0; j < 4; j++)                                           \
                ldmatrix_x4(bf[buf][j*4+0], bf[buf][j*4+1],                       \
                            bf[buf][j*4+2], bf[buf][j*4+3],                       \
                            bLd + (st) * BST + j * 16 * 80 + (ks) * 32);          \
        } while (0)

    #define MMA_ALL(buf)                                                          \
        do {                                                                      \
            _Pragma("unroll")                                                     \
            for (int i = 0; i < 4; i++)                                           \
                _Pragma("unroll")                                                 \
                for (int j = 0; j < 4; j++) {                                     \
                    mma_f16(acc[i][2*j    ], &af[buf][i*4],                       \
                            bf[buf][j*4+0], bf[buf][j*4+2]);                      \
                    mma_f16(acc[i][2*j + 1], &af[buf][i*4],                       \
                            bf[buf][j*4+1], bf[buf][j*4+3]);                      \
                }                                                                 \
        } while (0)

    // prologue: stages 0,1 in flight; stage 0 ready; frags(buf0, ks=0) loaded.
    ISSUE(0, 0); CP_COMMIT();
    ISSUE(1, 1); CP_COMMIT();
    CP_WAIT1();
    __syncthreads();
    LOAD_FRAGS(0, 0, 0);

    for (int t = 0; t < NT; t++) {
        const int st = t % 3;

        // ks = 0 phase: prefetch ks=1 frags, then MMA on ks=0 frags.
        LOAD_FRAGS(1, st, 1);
        MMA_ALL(0);

        // ks = 1 phase: keep gmem pipe fed, advance stage, prefetch next
        // tile's ks=0 frags, then MMA on ks=1 frags.
        if (t + 2 < NT) ISSUE(t + 2, (t + 2) % 3);
        CP_COMMIT();                // unconditional: keeps wait_group ledger
        if (t + 1 < NT) {
            CP_WAIT1();             // tile t+1's stage complete
            __syncthreads();        // all warps past stage-(t-1) frag reads
            LOAD_FRAGS(0, (t + 1) % 3, 0);
        }
        MMA_ALL(1);
    }

    // Epilogue: n -> (batch, channel); whole CTA sits in one batch.
    const int bidx = n0 >> 9;
    const int c0   = n0 & 511;
    const float* xb = x   + (size_t)bidx * SC;
    float*       ob = out + (size_t)bidx * SC;

    #pragma unroll
    for (int i = 0; i < 4; i++) {
        const int t0 = m0 + wm + i * 16 + (lane >> 2);
        const float bias0 = __ldg(linb + t0);
        const float bias1 = __ldg(linb + t0 + 8);
        #pragma unroll
        for (int j = 0; j < 8; j++) {
            const int c = c0 + wn + j * 8 + (lane & 3) * 2;
            float2 xv0 = *reinterpret_cast<const float2*>(xb + (size_t)t0 * CC + c);
            float2 o0;
            o0.x = xv0.x + fmaxf(acc[i][j][0] + bias0, 0.f);
            o0.y = xv0.y + fmaxf(acc[i][j][1] + bias0, 0.f);
            *reinterpret_cast<float2*>(ob + (size_t)t0 * CC + c) = o0;

            float2 xv1 = *reinterpret_cast<const float2*>(xb + (size_t)(t0 + 8) * CC + c);
            float2 o1;
            o1.x = xv1.x + fmaxf(acc[i][j][2] + bias1, 0.f);
            o1.y = xv1.y + fmaxf(acc[i][j][3] + bias1, 0.f);
            *reinterpret_cast<float2*>(ob + (size_t)(t0 + 8) * CC + c) = o1;
        }
    }
}

// ---------------------------------------------------------------------------
// Launch (2 kernels/iter -> ncu -s 5 -c 1 lands on the GEMM, launch #6)
// ---------------------------------------------------------------------------
extern "C" void kernel_launch(void* const* d_in, const int* in_sizes, int n_in,
                              void* d_out, int out_size) {
    const float* x     = (const float*)d_in[0];
    const float* ln_w  = (const float*)d_in[1];
    const float* ln_b  = (const float*)d_in[2];
    const float* lin_w = (const float*)d_in[3];
    const float* lin_b = (const float*)d_in[4];
    float* out = (float*)d_out;

    cudaFuncSetAttribute(gemm_f16, cudaFuncAttributeMaxDynamicSharedMemorySize, GSMEM);

    prepass_kernel<<<PCTAS, 256>>>(x, lin_w, ln_w, ln_b);

    // M=1024 (8 x 128), N=32768 (256 x 128)
    gemm_f16<<<dim3(8, 256), 128, GSMEM>>>(lin_b, x, out);
}